// round 4
// baseline (speedup 1.0000x reference)
#include <cuda_runtime.h>
#include <stdint.h>

// ---------------------------------------------------------------------------
// Scratch
// ---------------------------------------------------------------------------
__device__ float g_bev_feat[8 * 128 * 1024];   // (bt, c, n)
__device__ float g_kv[8 * 192 * 1024];         // (bt, c, n)
__device__ float g_Q[8 * 4 * 1024 * 32];       // (bt,h,n,d) scaled by 1/sqrt(d)*log2e
__device__ float g_K[8 * 4 * 1024 * 32];
__device__ float g_V[8 * 4 * 1024 * 32];
__device__ float g_attn[8 * 1024 * 128];       // (bt, n, c)
__device__ float g_fused[8 * 128 * 1024];      // (bt, c, n)

// ---------------------------------------------------------------------------
// Helpers
// ---------------------------------------------------------------------------
__device__ __forceinline__ float f2tf(float x) {
    uint32_t u;
    asm("cvt.rna.tf32.f32 %0,%1;" : "=r"(u) : "f"(x));
    return __uint_as_float(u);
}
__device__ __forceinline__ float ex2f(float x) {
    float y;
    asm("ex2.approx.f32 %0,%1;" : "=f"(y) : "f"(x));
    return y;
}
__device__ __forceinline__ void mma8(float* c, float a0, float a1, float a2,
                                     float a3, float b0, float b1) {
    asm("mma.sync.aligned.m16n8k8.row.col.f32.tf32.tf32.f32 "
        "{%0,%1,%2,%3},{%4,%5,%6,%7},{%8,%9},{%0,%1,%2,%3};"
        : "+f"(c[0]), "+f"(c[1]), "+f"(c[2]), "+f"(c[3])
        : "r"(__float_as_uint(a0)), "r"(__float_as_uint(a1)),
          "r"(__float_as_uint(a2)), "r"(__float_as_uint(a3)),
          "r"(__float_as_uint(b0)), "r"(__float_as_uint(b1)));
}

// ---------------------------------------------------------------------------
// Bilinear resize 16x16 -> 32x32 (half-pixel), writes g_kv channels 128..191
// ---------------------------------------------------------------------------
__global__ __launch_bounds__(256) void resize_front_kernel(const float* __restrict__ front) {
    int idx = blockIdx.x * 256 + threadIdx.x;
    if (idx >= 8 * 64 * 1024) return;
    int px = idx & 1023, c = (idx >> 10) & 63, bt = idx >> 16;
    int y = px >> 5, x = px & 31;
    float sy = y * 0.5f - 0.25f, sx = x * 0.5f - 0.25f;
    int y0 = __float2int_rd(sy), x0 = __float2int_rd(sx);
    float fy = sy - y0, fx = sx - x0;
    int y0c = max(y0, 0), y1c = min(y0 + 1, 15);
    int x0c = max(x0, 0), x1c = min(x0 + 1, 15);
    const float* src = front + (bt * 64 + c) * 256;
    float a = src[y0c * 16 + x0c], b = src[y0c * 16 + x1c];
    float cc = src[y1c * 16 + x0c], d = src[y1c * 16 + x1c];
    float top = a + fx * (b - a), bot = cc + fx * (d - cc);
    g_kv[(size_t)(bt * 192 + 128 + c) * 1024 + px] = top + fy * (bot - top);
}

// ---------------------------------------------------------------------------
// Conv 3x3 SAME via implicit GEMM on tf32 mma, runtime-parameterized, dual-path.
// Block tile: 32oc x 128px (4 rows). 8 warps: om=warp>>2 (16oc), pw=warp&3 (row).
// Ego channels (CTOT>CIN) synthesized inline from ego[] (broadcast per channel).
// blockIdx.x < xsplit -> path0, else path1. grid (xsplit[+4], 8 rowg, 8 bt).
// ---------------------------------------------------------------------------
__global__ __launch_bounds__(256) void conv_dual_kernel(
    const float* __restrict__ in0, const float* __restrict__ w0,
    const float* __restrict__ bias0, float* __restrict__ out0, int ld0, int cin0, int ctot0,
    const float* __restrict__ in1, const float* __restrict__ w1,
    const float* __restrict__ bias1, float* __restrict__ out1, int ld1, int cin1, int ctot1,
    const float* __restrict__ ego, int xsplit)
{
    const int path = (int)blockIdx.x >= xsplit;
    const float* in = path ? in1 : in0;
    const float* w = path ? w1 : w0;
    const float* bias = path ? bias1 : bias0;
    float* out = path ? out1 : out0;
    const int ld_out = path ? ld1 : ld0;
    const int CIN = path ? cin1 : cin0;
    const int CTOT = path ? ctot1 : ctot0;
    const int NCH = CTOT >> 3;
    const int oc_base = (path ? blockIdx.x - xsplit : blockIdx.x) * 32;
    const int y0 = blockIdx.y * 4;
    const int bt = blockIdx.z;
    const int tid = threadIdx.x;
    const int warp = tid >> 5, lane = tid & 31;
    const int g = lane >> 2, t4 = lane & 3;
    const int om = warp >> 2, pw = warp & 3;

    __shared__ float s_in[8 * 216];   // 8 ic x (6 rows x 34), stride 216
    __shared__ float s_w[32 * 76];    // 32 oc x 72k, stride 76

    // staging map: 1632 input elems over 256 threads (7 slots)
    int sdst[7], ssrc[7], sicl[7];
    unsigned vmask = 0, amask = 0;
#pragma unroll
    for (int s = 0; s < 7; s++) {
        int idx = tid + s * 256;
        sdst[s] = 0; ssrc[s] = 0; sicl[s] = 0;
        if (idx < 1632) {
            amask |= 1u << s;
            int icl = idx / 204, rem = idx - icl * 204;
            int rr = rem / 34, cc = rem - rr * 34;
            int Y = y0 - 1 + rr, X = cc - 1;
            sdst[s] = icl * 216 + rem;
            sicl[s] = icl;
            if ((unsigned)Y < 32u && (unsigned)X < 32u) {
                vmask |= 1u << s;
                ssrc[s] = icl * 1024 + Y * 32 + X;
            }
        }
    }
    const int woc = tid >> 3, wicl = tid & 7;

    float C[4][4];
#pragma unroll
    for (int nt = 0; nt < 4; nt++)
#pragma unroll
        for (int i = 0; i < 4; i++) C[nt][i] = 0.f;

    float pin[7], pwv[9];
    // prefetch chunk 0 (always real input channels)
    {
        const float* src = in + (size_t)bt * CIN * 1024;
#pragma unroll
        for (int s = 0; s < 7; s++)
            pin[s] = (vmask >> s & 1) ? __ldg(src + ssrc[s]) : 0.f;
        const float* wp = w + ((size_t)(oc_base + woc) * CTOT + wicl) * 9;
#pragma unroll
        for (int j = 0; j < 9; j++) pwv[j] = __ldg(wp + j);
    }

    for (int ch = 0; ch < NCH; ch++) {
#pragma unroll
        for (int s = 0; s < 7; s++)
            if (amask >> s & 1) s_in[sdst[s]] = f2tf(pin[s]);
#pragma unroll
        for (int j = 0; j < 9; j++) s_w[woc * 76 + j * 8 + wicl] = f2tf(pwv[j]);
        __syncthreads();

        if (ch + 1 < NCH) {
            int ic0 = (ch + 1) * 8;
            if (ic0 < CIN) {
                const float* src = in + (size_t)(bt * CIN + ic0) * 1024;
#pragma unroll
                for (int s = 0; s < 7; s++)
                    pin[s] = (vmask >> s & 1) ? __ldg(src + ssrc[s]) : 0.f;
            } else {
                const float* e = ego + bt * 16 + (ic0 - CIN);
#pragma unroll
                for (int s = 0; s < 7; s++)
                    pin[s] = (vmask >> s & 1) ? __ldg(e + sicl[s]) : 0.f;
            }
            const float* wp = w + ((size_t)(oc_base + woc) * CTOT + ic0 + wicl) * 9;
#pragma unroll
            for (int j = 0; j < 9; j++) pwv[j] = __ldg(wp + j);
        }

#pragma unroll
        for (int kt = 0; kt < 9; kt++) {
            const int dy = kt / 3, dx = kt % 3;
            float a0 = s_w[(om * 16 + g) * 76 + kt * 8 + t4];
            float a1 = s_w[(om * 16 + g + 8) * 76 + kt * 8 + t4];
            float a2 = s_w[(om * 16 + g) * 76 + kt * 8 + t4 + 4];
            float a3 = s_w[(om * 16 + g + 8) * 76 + kt * 8 + t4 + 4];
#pragma unroll
            for (int nt = 0; nt < 4; nt++) {
                int base = (pw + dy) * 34 + nt * 8 + g + dx;
                float b0 = s_in[t4 * 216 + base];
                float b1 = s_in[(t4 + 4) * 216 + base];
                mma8(C[nt], a0, a1, a2, a3, b0, b1);
            }
        }
        __syncthreads();
    }

    const int o0 = oc_base + om * 16 + g, o1 = o0 + 8;
    const float bv0 = bias[o0], bv1 = bias[o1];
    const int y = y0 + pw;
#pragma unroll
    for (int nt = 0; nt < 4; nt++) {
        int px = y * 32 + nt * 8 + 2 * t4;
        float2 v0 = {fmaxf(C[nt][0] + bv0, 0.f), fmaxf(C[nt][1] + bv0, 0.f)};
        float2 v1 = {fmaxf(C[nt][2] + bv1, 0.f), fmaxf(C[nt][3] + bv1, 0.f)};
        *(float2*)(out + (size_t)(bt * ld_out + o0) * 1024 + px) = v0;
        *(float2*)(out + (size_t)(bt * ld_out + o1) * 1024 + px) = v1;
    }
}

// ---------------------------------------------------------------------------
// Fused Q/K/V projection. blockIdx.y selects {Q,K,V}.
// Block tile: 64o x 128n. 8 warps: om=warp>>1 (16o), nw=warp&1 (64n).
// grid (16 = 8ng x 2og, 3, 8 bt).
// ---------------------------------------------------------------------------
__global__ __launch_bounds__(256) void proj_qkv_fused(
    const float* __restrict__ Wq, const float* __restrict__ Wk,
    const float* __restrict__ Wv, float scaleQ)
{
    const int which = blockIdx.y;
    const float* X = which == 0 ? g_bev_feat : g_kv;
    const float* W = which == 0 ? Wq : (which == 1 ? Wk : Wv);
    float* out = which == 0 ? g_Q : (which == 1 ? g_K : g_V);
    const int Cdim = which == 0 ? 128 : 192;
    const float scale = which == 0 ? scaleQ : 1.f;

    const int n0 = (blockIdx.x & 7) * 128;
    const int o_base = (blockIdx.x >> 3) * 64;
    const int bt = blockIdx.z;
    const int tid = threadIdx.x;
    const int warp = tid >> 5, lane = tid & 31;
    const int g = lane >> 2, t4 = lane & 3;
    const int om = warp >> 1, nw = warp & 1;

    __shared__ float sX[8 * 136];
    __shared__ float sW[64 * 12];

    float C[8][4];
#pragma unroll
    for (int nt = 0; nt < 8; nt++)
#pragma unroll
        for (int i = 0; i < 4; i++) C[nt][i] = 0.f;

    const int xk = tid >> 5, xn = lane * 4;
    const int wo = tid & 63, wk2 = (tid >> 6) * 2;

    float4 px4 = *(const float4*)(X + (size_t)(bt * Cdim + xk) * 1024 + n0 + xn);
    float2 pw2 = *(const float2*)(W + (size_t)(o_base + wo) * Cdim + wk2);

    const int NK = Cdim >> 3;
    for (int ck = 0; ck < NK; ck++) {
        sX[xk * 136 + xn + 0] = f2tf(px4.x);
        sX[xk * 136 + xn + 1] = f2tf(px4.y);
        sX[xk * 136 + xn + 2] = f2tf(px4.z);
        sX[xk * 136 + xn + 3] = f2tf(px4.w);
        sW[wo * 12 + wk2 + 0] = f2tf(pw2.x);
        sW[wo * 12 + wk2 + 1] = f2tf(pw2.y);
        __syncthreads();
        if (ck + 1 < NK) {
            int c0 = (ck + 1) * 8;
            px4 = *(const float4*)(X + (size_t)(bt * Cdim + c0 + xk) * 1024 + n0 + xn);
            pw2 = *(const float2*)(W + (size_t)(o_base + wo) * Cdim + c0 + wk2);
        }
        {
            int ob = (om * 16 + g) * 12;
            float a0 = sW[ob + t4];
            float a1 = sW[ob + 96 + t4];
            float a2 = sW[ob + t4 + 4];
            float a3 = sW[ob + 96 + t4 + 4];
#pragma unroll
            for (int nt = 0; nt < 8; nt++) {
                float b0 = sX[t4 * 136 + nw * 64 + nt * 8 + g];
                float b1 = sX[(t4 + 4) * 136 + nw * 64 + nt * 8 + g];
                mma8(C[nt], a0, a1, a2, a3, b0, b1);
            }
        }
        __syncthreads();
    }

    const int o0 = o_base + om * 16 + g, o1 = o0 + 8;
    size_t b0 = (size_t)(bt * 4 + (o0 >> 5)) * 32768 + (o0 & 31);
    size_t b1 = (size_t)(bt * 4 + (o1 >> 5)) * 32768 + (o1 & 31);
#pragma unroll
    for (int nt = 0; nt < 8; nt++) {
        int n = n0 + nw * 64 + nt * 8 + 2 * t4;
        out[b0 + (size_t)n * 32] = C[nt][0] * scale;
        out[b0 + (size_t)(n + 1) * 32] = C[nt][1] * scale;
        out[b1 + (size_t)n * 32] = C[nt][2] * scale;
        out[b1 + (size_t)(n + 1) * 32] = C[nt][3] * scale;
    }
}

// ---------------------------------------------------------------------------
// Output projection: g_fused(bt,o,n) = wo @ g_attn(bt,n,:)^T + bo.
// Same 64o x 128n tile. grid (16, 8 bt).
// ---------------------------------------------------------------------------
__global__ __launch_bounds__(256) void proj_out_mma(
    const float* __restrict__ W, const float* __restrict__ bias)
{
    const int n0 = (blockIdx.x & 7) * 128;
    const int o_base = (blockIdx.x >> 3) * 64;
    const int bt = blockIdx.y;
    const int tid = threadIdx.x;
    const int warp = tid >> 5, lane = tid & 31;
    const int g = lane >> 2, t4 = lane & 3;
    const int om = warp >> 1, nw = warp & 1;

    __shared__ float sX[8 * 136];
    __shared__ float sW[64 * 12];

    float C[8][4];
#pragma unroll
    for (int nt = 0; nt < 8; nt++)
#pragma unroll
        for (int i = 0; i < 4; i++) C[nt][i] = 0.f;

    const int xn = tid & 127, xc = (tid >> 7) * 4;
    const int wo = tid & 63, wk2 = (tid >> 6) * 2;

    float4 px4 = *(const float4*)(g_attn + (size_t)(bt * 1024 + n0 + xn) * 128 + xc);
    float2 pw2 = *(const float2*)(W + (size_t)(o_base + wo) * 128 + wk2);

    for (int ck = 0; ck < 16; ck++) {
        sX[(xc + 0) * 136 + xn] = f2tf(px4.x);
        sX[(xc + 1) * 136 + xn] = f2tf(px4.y);
        sX[(xc + 2) * 136 + xn] = f2tf(px4.z);
        sX[(xc + 3) * 136 + xn] = f2tf(px4.w);
        sW[wo * 12 + wk2 + 0] = f2tf(pw2.x);
        sW[wo * 12 + wk2 + 1] = f2tf(pw2.y);
        __syncthreads();
        if (ck + 1 < 16) {
            int c0 = (ck + 1) * 8;
            px4 = *(const float4*)(g_attn + (size_t)(bt * 1024 + n0 + xn) * 128 + c0 + xc);
            pw2 = *(const float2*)(W + (size_t)(o_base + wo) * 128 + c0 + wk2);
        }
        {
            int ob = (om * 16 + g) * 12;
            float a0 = sW[ob + t4];
            float a1 = sW[ob + 96 + t4];
            float a2 = sW[ob + t4 + 4];
            float a3 = sW[ob + 96 + t4 + 4];
#pragma unroll
            for (int nt = 0; nt < 8; nt++) {
                float b0 = sX[t4 * 136 + nw * 64 + nt * 8 + g];
                float b1 = sX[(t4 + 4) * 136 + nw * 64 + nt * 8 + g];
                mma8(C[nt], a0, a1, a2, a3, b0, b1);
            }
        }
        __syncthreads();
    }

    const int o0 = o_base + om * 16 + g, o1 = o0 + 8;
    const float bv0 = bias[o0], bv1 = bias[o1];
#pragma unroll
    for (int nt = 0; nt < 8; nt++) {
        int n = n0 + nw * 64 + nt * 8 + 2 * t4;
        float2 v0 = {C[nt][0] + bv0, C[nt][1] + bv0};
        float2 v1 = {C[nt][2] + bv1, C[nt][3] + bv1};
        *(float2*)(g_fused + (size_t)(bt * 128 + o0) * 1024 + n) = v0;
        *(float2*)(g_fused + (size_t)(bt * 128 + o1) * 1024 + n) = v1;
    }
}

// ---------------------------------------------------------------------------
// Flash attention on tf32 mma (unchanged from R3; correct + ~mma-floor bound).
// ---------------------------------------------------------------------------
__global__ __launch_bounds__(256) void attn_mma_kernel() {
    const int q0 = blockIdx.x * 128;
    const int h = blockIdx.y;
    const int bt = blockIdx.z;
    const int tid = threadIdx.x;
    const int warp = tid >> 5, lane = tid & 31;
    const int g = lane >> 2, t4 = lane & 3;
    const size_t hb = (size_t)(bt * 4 + h) * 32768;

    __shared__ __align__(16) float sK[128 * 36];
    __shared__ __align__(16) float sV[128 * 36];

    float qa[4][4];
    {
        const float* qp = g_Q + hb + (size_t)(q0 + warp * 16) * 32;
#pragma unroll
        for (int dc = 0; dc < 4; dc++) {
            qa[dc][0] = f2tf(qp[g * 32 + dc * 8 + t4]);
            qa[dc][1] = f2tf(qp[(g + 8) * 32 + dc * 8 + t4]);
            qa[dc][2] = f2tf(qp[g * 32 + dc * 8 + t4 + 4]);
            qa[dc][3] = f2tf(qp[(g + 8) * 32 + dc * 8 + t4 + 4]);
        }
    }

    float O[4][4];
#pragma unroll
    for (int dt = 0; dt < 4; dt++)
#pragma unroll
        for (int i = 0; i < 4; i++) O[dt][i] = 0.f;
    float m0 = -1e30f, m1 = -1e30f, l0 = 0.f, l1 = 0.f;

    const int key = tid >> 1, dg = (tid & 1) * 16;
    const int klo = key & 7;
    const int prow = (key & ~7) | ((klo >> 1) | ((klo & 1) << 2));

    for (int kt = 0; kt < 8; kt++) {
        const float* kp = g_K + hb + (size_t)(kt * 128 + key) * 32 + dg;
        const float* vp = g_V + hb + (size_t)(kt * 128 + key) * 32 + dg;
#pragma unroll
        for (int j = 0; j < 4; j++) {
            float4 kv = *(const float4*)(kp + 4 * j);
            float4 vv = *(const float4*)(vp + 4 * j);
            float4 kr = {f2tf(kv.x), f2tf(kv.y), f2tf(kv.z), f2tf(kv.w)};
            float4 vr = {f2tf(vv.x), f2tf(vv.y), f2tf(vv.z), f2tf(vv.w)};
            *(float4*)&sK[key * 36 + dg + 4 * j] = kr;
            *(float4*)&sV[prow * 36 + dg + 4 * j] = vr;
        }
        __syncthreads();

        float S[16][4];
#pragma unroll
        for (int nt = 0; nt < 16; nt++) {
#pragma unroll
            for (int i = 0; i < 4; i++) S[nt][i] = 0.f;
#pragma unroll
            for (int dc = 0; dc < 4; dc++) {
                float b0 = sK[(nt * 8 + g) * 36 + dc * 8 + t4];
                float b1 = sK[(nt * 8 + g) * 36 + dc * 8 + t4 + 4];
                mma8(S[nt], qa[dc][0], qa[dc][1], qa[dc][2], qa[dc][3], b0, b1);
            }
        }

        float mx0 = -1e30f, mx1 = -1e30f;
#pragma unroll
        for (int nt = 0; nt < 16; nt++) {
            mx0 = fmaxf(mx0, fmaxf(S[nt][0], S[nt][1]));
            mx1 = fmaxf(mx1, fmaxf(S[nt][2], S[nt][3]));
        }
        mx0 = fmaxf(mx0, __shfl_xor_sync(0xffffffff, mx0, 1));
        mx0 = fmaxf(mx0, __shfl_xor_sync(0xffffffff, mx0, 2));
        mx1 = fmaxf(mx1, __shfl_xor_sync(0xffffffff, mx1, 1));
        mx1 = fmaxf(mx1, __shfl_xor_sync(0xffffffff, mx1, 2));
        float mn0 = fmaxf(m0, mx0), mn1 = fmaxf(m1, mx1);
        float sc0 = ex2f(m0 - mn0), sc1 = ex2f(m1 - mn1);
        m0 = mn0; m1 = mn1;

        float ls0 = 0.f, ls1 = 0.f;
#pragma unroll
        for (int nt = 0; nt < 16; nt++) {
            S[nt][0] = f2tf(ex2f(S[nt][0] - mn0));
            S[nt][1] = f2tf(ex2f(S[nt][1] - mn0));
            S[nt][2] = f2tf(ex2f(S[nt][2] - mn1));
            S[nt][3] = f2tf(ex2f(S[nt][3] - mn1));
            ls0 += S[nt][0] + S[nt][1];
            ls1 += S[nt][2] + S[nt][3];
        }
        ls0 += __shfl_xor_sync(0xffffffff, ls0, 1);
        ls0 += __shfl_xor_sync(0xffffffff, ls0, 2);
        ls1 += __shfl_xor_sync(0xffffffff, ls1, 1);
        ls1 += __shfl_xor_sync(0xffffffff, ls1, 2);
        l0 = l0 * sc0 + ls0;
        l1 = l1 * sc1 + ls1;

#pragma unroll
        for (int dt = 0; dt < 4; dt++) {
            O[dt][0] *= sc0; O[dt][1] *= sc0;
            O[dt][2] *= sc1; O[dt][3] *= sc1;
        }

#pragma unroll
        for (int kc = 0; kc < 16; kc++) {
            float a0 = S[kc][0], a1 = S[kc][2], a2 = S[kc][1], a3 = S[kc][3];
#pragma unroll
            for (int dt = 0; dt < 4; dt++) {
                float b0 = sV[(kc * 8 + t4) * 36 + dt * 8 + g];
                float b1 = sV[(kc * 8 + t4 + 4) * 36 + dt * 8 + g];
                mma8(O[dt], a0, a1, a2, a3, b0, b1);
            }
        }
        __syncthreads();
    }

    float inv0 = 1.f / l0, inv1 = 1.f / l1;
    int q = q0 + warp * 16 + g;
    size_t ob = (size_t)(bt * 1024 + q) * 128 + h * 32;
#pragma unroll
    for (int dt = 0; dt < 4; dt++) {
        float2 v0 = {O[dt][0] * inv0, O[dt][1] * inv0};
        float2 v1 = {O[dt][2] * inv1, O[dt][3] * inv1};
        *(float2*)(g_attn + ob + dt * 8 + 2 * t4) = v0;
        *(float2*)(g_attn + ob + 8 * 128 + dt * 8 + 2 * t4) = v1;
    }
}

// ---------------------------------------------------------------------------
// Launch
// ---------------------------------------------------------------------------
extern "C" void kernel_launch(void* const* d_in, const int* in_sizes, int n_in,
                              void* d_out, int out_size) {
    const float* bev   = (const float*)d_in[0];
    const float* hd    = (const float*)d_in[1];
    const float* ego   = (const float*)d_in[2];
    const float* front = (const float*)d_in[3];
    const float* w_bev = (const float*)d_in[4];
    const float* b_bev = (const float*)d_in[5];
    const float* w_hd  = (const float*)d_in[6];
    const float* b_hd  = (const float*)d_in[7];
    const float* wq    = (const float*)d_in[8];
    const float* wk    = (const float*)d_in[9];
    const float* wv    = (const float*)d_in[10];
    const float* wo    = (const float*)d_in[11];
    const float* bo    = (const float*)d_in[12];
    const float* w_out = (const float*)d_in[13];
    const float* b_out = (const float*)d_in[14];
    float* out = (float*)d_out;

    float *p_bev_feat, *p_kv, *p_fused;
    cudaGetSymbolAddress((void**)&p_bev_feat, g_bev_feat);
    cudaGetSymbolAddress((void**)&p_kv, g_kv);
    cudaGetSymbolAddress((void**)&p_fused, g_fused);

    const float scaleQ = 0.17677669529663687f * 1.4426950408889634f;

    // 1. front resize (fills g_kv[128:192])
    resize_front_kernel<<<2048, 256>>>(front);

    // 2. both input convs in one launch (512 blocks)
    conv_dual_kernel<<<dim3(8, 8, 8), 256>>>(
        bev, w_bev, b_bev, p_bev_feat, 128, 128, 144,
        hd, w_hd, b_hd, p_kv, 192, 64, 64,
        ego, 4);

    // 3. Q/K/V projections in one launch (384 blocks)
    proj_qkv_fused<<<dim3(16, 3, 8), 256>>>(wq, wk, wv, scaleQ);

    // 4. attention (256 blocks)
    attn_mma_kernel<<<dim3(8, 4, 8), 256>>>();

    // 5. output projection (128 blocks)
    proj_out_mma<<<dim3(16, 8), 256>>>(wo, bo);

    // 6. final conv (256 blocks)
    conv_dual_kernel<<<dim3(4, 8, 8), 256>>>(
        p_fused, w_out, b_out, out, 128, 128, 144,
        p_fused, w_out, b_out, out, 128, 128, 144,
        ego, 4);
}

// round 5
// speedup vs baseline: 1.1933x; 1.1933x over previous
#include <cuda_runtime.h>
#include <stdint.h>

// ---------------------------------------------------------------------------
// Scratch
// ---------------------------------------------------------------------------
__device__ float g_bev_feat[8 * 128 * 1024];   // (bt, c, n)
__device__ float g_kv[8 * 192 * 1024];         // (bt, c, n)
__device__ float g_Q[8 * 4 * 1024 * 32];       // (bt,h,n,d) tf32, scaled sqrt(d)^-1*log2e
__device__ float g_Kp[8 * 4 * 16 * 2048];      // packed B-fragments per 64-key tile
__device__ float g_Vp[8 * 4 * 16 * 2048];      // packed (incl. sigma row permutation)
__device__ float g_attn[8 * 1024 * 128];       // (bt, n, c)
__device__ float g_fused[8 * 128 * 1024];      // (bt, c, n)

// ---------------------------------------------------------------------------
// Helpers
// ---------------------------------------------------------------------------
__device__ __forceinline__ float f2tf(float x) {
    uint32_t u;
    asm("cvt.rna.tf32.f32 %0,%1;" : "=r"(u) : "f"(x));
    return __uint_as_float(u);
}
__device__ __forceinline__ float ex2f(float x) {
    float y;
    asm("ex2.approx.f32 %0,%1;" : "=f"(y) : "f"(x));
    return y;
}
__device__ __forceinline__ void mma8(float* c, float a0, float a1, float a2,
                                     float a3, float b0, float b1) {
    asm("mma.sync.aligned.m16n8k8.row.col.f32.tf32.tf32.f32 "
        "{%0,%1,%2,%3},{%4,%5,%6,%7},{%8,%9},{%0,%1,%2,%3};"
        : "+f"(c[0]), "+f"(c[1]), "+f"(c[2]), "+f"(c[3])
        : "r"(__float_as_uint(a0)), "r"(__float_as_uint(a1)),
          "r"(__float_as_uint(a2)), "r"(__float_as_uint(a3)),
          "r"(__float_as_uint(b0)), "r"(__float_as_uint(b1)));
}
#define CP16(dst, src)                                                        \
    {                                                                         \
        uint32_t _s = (uint32_t)__cvta_generic_to_shared(dst);                \
        asm volatile("cp.async.cg.shared.global [%0], [%1], 16;" ::"r"(_s),   \
                     "l"(src));                                               \
    }

// ---------------------------------------------------------------------------
// Bilinear resize 16x16 -> 32x32 (half-pixel), writes g_kv channels 128..191
// ---------------------------------------------------------------------------
__global__ __launch_bounds__(256) void resize_front_kernel(const float* __restrict__ front) {
    int idx = blockIdx.x * 256 + threadIdx.x;
    if (idx >= 8 * 64 * 1024) return;
    int px = idx & 1023, c = (idx >> 10) & 63, bt = idx >> 16;
    int y = px >> 5, x = px & 31;
    float sy = y * 0.5f - 0.25f, sx = x * 0.5f - 0.25f;
    int y0 = __float2int_rd(sy), x0 = __float2int_rd(sx);
    float fy = sy - y0, fx = sx - x0;
    int y0c = max(y0, 0), y1c = min(y0 + 1, 15);
    int x0c = max(x0, 0), x1c = min(x0 + 1, 15);
    const float* src = front + (bt * 64 + c) * 256;
    float a = src[y0c * 16 + x0c], b = src[y0c * 16 + x1c];
    float cc = src[y1c * 16 + x0c], d = src[y1c * 16 + x1c];
    float top = a + fx * (b - a), bot = cc + fx * (d - cc);
    g_kv[(size_t)(bt * 192 + 128 + c) * 1024 + px] = top + fy * (bot - top);
}

// ---------------------------------------------------------------------------
// Conv 3x3 SAME via implicit GEMM on tf32 mma, runtime-parameterized, dual-path.
// (unchanged from R4)
// ---------------------------------------------------------------------------
__global__ __launch_bounds__(256) void conv_dual_kernel(
    const float* __restrict__ in0, const float* __restrict__ w0,
    const float* __restrict__ bias0, float* __restrict__ out0, int ld0, int cin0, int ctot0,
    const float* __restrict__ in1, const float* __restrict__ w1,
    const float* __restrict__ bias1, float* __restrict__ out1, int ld1, int cin1, int ctot1,
    const float* __restrict__ ego, int xsplit)
{
    const int path = (int)blockIdx.x >= xsplit;
    const float* in = path ? in1 : in0;
    const float* w = path ? w1 : w0;
    const float* bias = path ? bias1 : bias0;
    float* out = path ? out1 : out0;
    const int ld_out = path ? ld1 : ld0;
    const int CIN = path ? cin1 : cin0;
    const int CTOT = path ? ctot1 : ctot0;
    const int NCH = CTOT >> 3;
    const int oc_base = (path ? blockIdx.x - xsplit : blockIdx.x) * 32;
    const int y0 = blockIdx.y * 4;
    const int bt = blockIdx.z;
    const int tid = threadIdx.x;
    const int warp = tid >> 5, lane = tid & 31;
    const int g = lane >> 2, t4 = lane & 3;
    const int om = warp >> 2, pw = warp & 3;

    __shared__ float s_in[8 * 216];
    __shared__ float s_w[32 * 76];

    int sdst[7], ssrc[7], sicl[7];
    unsigned vmask = 0, amask = 0;
#pragma unroll
    for (int s = 0; s < 7; s++) {
        int idx = tid + s * 256;
        sdst[s] = 0; ssrc[s] = 0; sicl[s] = 0;
        if (idx < 1632) {
            amask |= 1u << s;
            int icl = idx / 204, rem = idx - icl * 204;
            int rr = rem / 34, cc = rem - rr * 34;
            int Y = y0 - 1 + rr, X = cc - 1;
            sdst[s] = icl * 216 + rem;
            sicl[s] = icl;
            if ((unsigned)Y < 32u && (unsigned)X < 32u) {
                vmask |= 1u << s;
                ssrc[s] = icl * 1024 + Y * 32 + X;
            }
        }
    }
    const int woc = tid >> 3, wicl = tid & 7;

    float C[4][4];
#pragma unroll
    for (int nt = 0; nt < 4; nt++)
#pragma unroll
        for (int i = 0; i < 4; i++) C[nt][i] = 0.f;

    float pin[7], pwv[9];
    {
        const float* src = in + (size_t)bt * CIN * 1024;
#pragma unroll
        for (int s = 0; s < 7; s++)
            pin[s] = (vmask >> s & 1) ? __ldg(src + ssrc[s]) : 0.f;
        const float* wp = w + ((size_t)(oc_base + woc) * CTOT + wicl) * 9;
#pragma unroll
        for (int j = 0; j < 9; j++) pwv[j] = __ldg(wp + j);
    }

    for (int ch = 0; ch < NCH; ch++) {
#pragma unroll
        for (int s = 0; s < 7; s++)
            if (amask >> s & 1) s_in[sdst[s]] = f2tf(pin[s]);
#pragma unroll
        for (int j = 0; j < 9; j++) s_w[woc * 76 + j * 8 + wicl] = f2tf(pwv[j]);
        __syncthreads();

        if (ch + 1 < NCH) {
            int ic0 = (ch + 1) * 8;
            if (ic0 < CIN) {
                const float* src = in + (size_t)(bt * CIN + ic0) * 1024;
#pragma unroll
                for (int s = 0; s < 7; s++)
                    pin[s] = (vmask >> s & 1) ? __ldg(src + ssrc[s]) : 0.f;
            } else {
                const float* e = ego + bt * 16 + (ic0 - CIN);
#pragma unroll
                for (int s = 0; s < 7; s++)
                    pin[s] = (vmask >> s & 1) ? __ldg(e + sicl[s]) : 0.f;
            }
            const float* wp = w + ((size_t)(oc_base + woc) * CTOT + ic0 + wicl) * 9;
#pragma unroll
            for (int j = 0; j < 9; j++) pwv[j] = __ldg(wp + j);
        }

#pragma unroll
        for (int kt = 0; kt < 9; kt++) {
            const int dy = kt / 3, dx = kt % 3;
            float a0 = s_w[(om * 16 + g) * 76 + kt * 8 + t4];
            float a1 = s_w[(om * 16 + g + 8) * 76 + kt * 8 + t4];
            float a2 = s_w[(om * 16 + g) * 76 + kt * 8 + t4 + 4];
            float a3 = s_w[(om * 16 + g + 8) * 76 + kt * 8 + t4 + 4];
#pragma unroll
            for (int nt = 0; nt < 4; nt++) {
                int base = (pw + dy) * 34 + nt * 8 + g + dx;
                float b0 = s_in[t4 * 216 + base];
                float b1 = s_in[(t4 + 4) * 216 + base];
                mma8(C[nt], a0, a1, a2, a3, b0, b1);
            }
        }
        __syncthreads();
    }

    const int o0 = oc_base + om * 16 + g, o1 = o0 + 8;
    const float bv0 = bias[o0], bv1 = bias[o1];
    const int y = y0 + pw;
#pragma unroll
    for (int nt = 0; nt < 4; nt++) {
        int px = y * 32 + nt * 8 + 2 * t4;
        float2 v0 = {fmaxf(C[nt][0] + bv0, 0.f), fmaxf(C[nt][1] + bv0, 0.f)};
        float2 v1 = {fmaxf(C[nt][2] + bv1, 0.f), fmaxf(C[nt][3] + bv1, 0.f)};
        *(float2*)(out + (size_t)(bt * ld_out + o0) * 1024 + px) = v0;
        *(float2*)(out + (size_t)(bt * ld_out + o1) * 1024 + px) = v1;
    }
}

// ---------------------------------------------------------------------------
// Fused Q/K/V projection. blockIdx.y selects {Q,K,V}.
// Q -> g_Q (normal layout, tf32-rounded, scaled).
// K -> g_Kp, V -> g_Vp: mma-B-fragment-packed per 64-key tile; V rows carry
// the sigma permutation so attention's S C-fragment feeds PV directly.
// ---------------------------------------------------------------------------
__global__ __launch_bounds__(256) void proj_qkv_fused(
    const float* __restrict__ Wq, const float* __restrict__ Wk,
    const float* __restrict__ Wv, float scaleQ)
{
    const int which = blockIdx.y;
    const float* X = which == 0 ? g_bev_feat : g_kv;
    const float* W = which == 0 ? Wq : (which == 1 ? Wk : Wv);
    const int Cdim = which == 0 ? 128 : 192;

    const int n0 = (blockIdx.x & 7) * 128;
    const int o_base = (blockIdx.x >> 3) * 64;
    const int bt = blockIdx.z;
    const int tid = threadIdx.x;
    const int warp = tid >> 5, lane = tid & 31;
    const int g = lane >> 2, t4 = lane & 3;
    const int om = warp >> 1, nw = warp & 1;

    __shared__ float sX[8 * 136];
    __shared__ float sW[64 * 12];

    float C[8][4];
#pragma unroll
    for (int nt = 0; nt < 8; nt++)
#pragma unroll
        for (int i = 0; i < 4; i++) C[nt][i] = 0.f;

    const int xk = tid >> 5, xn = lane * 4;
    const int wo = tid & 63, wk2 = (tid >> 6) * 2;

    float4 px4 = *(const float4*)(X + (size_t)(bt * Cdim + xk) * 1024 + n0 + xn);
    float2 pw2 = *(const float2*)(W + (size_t)(o_base + wo) * Cdim + wk2);

    const int NK = Cdim >> 3;
    for (int ck = 0; ck < NK; ck++) {
        sX[xk * 136 + xn + 0] = f2tf(px4.x);
        sX[xk * 136 + xn + 1] = f2tf(px4.y);
        sX[xk * 136 + xn + 2] = f2tf(px4.z);
        sX[xk * 136 + xn + 3] = f2tf(px4.w);
        sW[wo * 12 + wk2 + 0] = f2tf(pw2.x);
        sW[wo * 12 + wk2 + 1] = f2tf(pw2.y);
        __syncthreads();
        if (ck + 1 < NK) {
            int c0 = (ck + 1) * 8;
            px4 = *(const float4*)(X + (size_t)(bt * Cdim + c0 + xk) * 1024 + n0 + xn);
            pw2 = *(const float2*)(W + (size_t)(o_base + wo) * Cdim + c0 + wk2);
        }
        {
            int ob = (om * 16 + g) * 12;
            float a0 = sW[ob + t4];
            float a1 = sW[ob + 96 + t4];
            float a2 = sW[ob + t4 + 4];
            float a3 = sW[ob + 96 + t4 + 4];
#pragma unroll
            for (int nt = 0; nt < 8; nt++) {
                float b0 = sX[t4 * 136 + nw * 64 + nt * 8 + g];
                float b1 = sX[(t4 + 4) * 136 + nw * 64 + nt * 8 + g];
                mma8(C[nt], a0, a1, a2, a3, b0, b1);
            }
        }
        __syncthreads();
    }

    const int o0 = o_base + om * 16 + g, o1 = o0 + 8;
    if (which == 0) {
        size_t b0 = (size_t)(bt * 4 + (o0 >> 5)) * 32768 + (o0 & 31);
        size_t b1 = (size_t)(bt * 4 + (o1 >> 5)) * 32768 + (o1 & 31);
#pragma unroll
        for (int nt = 0; nt < 8; nt++) {
            int n = n0 + nw * 64 + nt * 8 + 2 * t4;
            g_Q[b0 + (size_t)n * 32] = f2tf(C[nt][0] * scaleQ);
            g_Q[b0 + (size_t)(n + 1) * 32] = f2tf(C[nt][1] * scaleQ);
            g_Q[b1 + (size_t)n * 32] = f2tf(C[nt][2] * scaleQ);
            g_Q[b1 + (size_t)(n + 1) * 32] = f2tf(C[nt][3] * scaleQ);
        }
    } else {
        // o0, o1 = o0+8 share the same head (d0 = (o0&31) < 8 ... d0,d0+8 in head)
        const int h = o0 >> 5;
        const int tile64 = (blockIdx.x & 7) * 2 + nw;
        const int dh = om & 1;  // d>>4 for both d0 and d0+8
        float* base = (which == 1 ? g_Kp : g_Vp) +
                      (size_t)((bt * 4 + h) * 16 + tile64) * 2048;
        if (which == 1) {
#pragma unroll
            for (int nt = 0; nt < 8; nt++) {
                int foff = ((nt * 2 + dh) * 32 + 8 * t4 + (g & 3)) * 4 + (g >> 2);
                base[foff]      = f2tf(C[nt][0]);
                base[foff + 16] = f2tf(C[nt][1]);
                base[foff + 2]  = f2tf(C[nt][2]);
                base[foff + 18] = f2tf(C[nt][3]);
            }
        } else {
#pragma unroll
            for (int nt = 0; nt < 8; nt++) {
                int foff = ((nt * 2 + dh) * 32 + g * 4 + t4) * 4;
                float4 v = {f2tf(C[nt][0]), f2tf(C[nt][1]),
                            f2tf(C[nt][2]), f2tf(C[nt][3])};
                *(float4*)(base + foff) = v;
            }
        }
    }
}

// ---------------------------------------------------------------------------
// Output projection (unchanged from R4)
// ---------------------------------------------------------------------------
__global__ __launch_bounds__(256) void proj_out_mma(
    const float* __restrict__ W, const float* __restrict__ bias)
{
    const int n0 = (blockIdx.x & 7) * 128;
    const int o_base = (blockIdx.x >> 3) * 64;
    const int bt = blockIdx.y;
    const int tid = threadIdx.x;
    const int warp = tid >> 5, lane = tid & 31;
    const int g = lane >> 2, t4 = lane & 3;
    const int om = warp >> 1, nw = warp & 1;

    __shared__ float sX[8 * 136];
    __shared__ float sW[64 * 12];

    float C[8][4];
#pragma unroll
    for (int nt = 0; nt < 8; nt++)
#pragma unroll
        for (int i = 0; i < 4; i++) C[nt][i] = 0.f;

    const int xn = tid & 127, xc = (tid >> 7) * 4;
    const int wo = tid & 63, wk2 = (tid >> 6) * 2;

    float4 px4 = *(const float4*)(g_attn + (size_t)(bt * 1024 + n0 + xn) * 128 + xc);
    float2 pw2 = *(const float2*)(W + (size_t)(o_base + wo) * 128 + wk2);

    for (int ck = 0; ck < 16; ck++) {
        sX[(xc + 0) * 136 + xn] = f2tf(px4.x);
        sX[(xc + 1) * 136 + xn] = f2tf(px4.y);
        sX[(xc + 2) * 136 + xn] = f2tf(px4.z);
        sX[(xc + 3) * 136 + xn] = f2tf(px4.w);
        sW[wo * 12 + wk2 + 0] = f2tf(pw2.x);
        sW[wo * 12 + wk2 + 1] = f2tf(pw2.y);
        __syncthreads();
        if (ck + 1 < 16) {
            int c0 = (ck + 1) * 8;
            px4 = *(const float4*)(g_attn + (size_t)(bt * 1024 + n0 + xn) * 128 + c0 + xc);
            pw2 = *(const float2*)(W + (size_t)(o_base + wo) * 128 + c0 + wk2);
        }
        {
            int ob = (om * 16 + g) * 12;
            float a0 = sW[ob + t4];
            float a1 = sW[ob + 96 + t4];
            float a2 = sW[ob + t4 + 4];
            float a3 = sW[ob + 96 + t4 + 4];
#pragma unroll
            for (int nt = 0; nt < 8; nt++) {
                float b0 = sX[t4 * 136 + nw * 64 + nt * 8 + g];
                float b1 = sX[(t4 + 4) * 136 + nw * 64 + nt * 8 + g];
                mma8(C[nt], a0, a1, a2, a3, b0, b1);
            }
        }
        __syncthreads();
    }

    const int o0 = o_base + om * 16 + g, o1 = o0 + 8;
    const float bv0 = bias[o0], bv1 = bias[o1];
#pragma unroll
    for (int nt = 0; nt < 8; nt++) {
        int n = n0 + nw * 64 + nt * 8 + 2 * t4;
        float2 v0 = {C[nt][0] + bv0, C[nt][1] + bv0};
        float2 v1 = {C[nt][2] + bv1, C[nt][3] + bv1};
        *(float2*)(g_fused + (size_t)(bt * 128 + o0) * 1024 + n) = v0;
        *(float2*)(g_fused + (size_t)(bt * 128 + o1) * 1024 + n) = v1;
    }
}

// ---------------------------------------------------------------------------
// Flash attention, fragment-native. Block 128 thr (4 warps x 16q = 64q),
// 16 key-tiles of 64, cp.async double-buffered, no-max softmax.
// grid (16 qg, 4 h, 8 bt).
// ---------------------------------------------------------------------------
__global__ __launch_bounds__(128) void attn_mma_kernel() {
    const int q0 = blockIdx.x * 64;
    const int h = blockIdx.y;
    const int bt = blockIdx.z;
    const int tid = threadIdx.x;
    const int warp = tid >> 5, lane = tid & 31;
    const int g = lane >> 2, t4 = lane & 3;

    __shared__ __align__(16) float4 sK[2][512];
    __shared__ __align__(16) float4 sV[2][512];

    // Q fragments (already tf32-rounded + scaled)
    float qa[4][4];
    {
        const float* qp = g_Q + ((size_t)(bt * 4 + h) * 1024 + q0 + warp * 16) * 32;
#pragma unroll
        for (int dc = 0; dc < 4; dc++) {
            qa[dc][0] = qp[g * 32 + dc * 8 + t4];
            qa[dc][1] = qp[(g + 8) * 32 + dc * 8 + t4];
            qa[dc][2] = qp[g * 32 + dc * 8 + t4 + 4];
            qa[dc][3] = qp[(g + 8) * 32 + dc * 8 + t4 + 4];
        }
    }

    float O[4][4];
#pragma unroll
    for (int dt = 0; dt < 4; dt++)
#pragma unroll
        for (int i = 0; i < 4; i++) O[dt][i] = 0.f;
    float l0 = 0.f, l1 = 0.f;

    const float4* kg = (const float4*)(g_Kp + (size_t)(bt * 4 + h) * 16 * 2048);
    const float4* vg = (const float4*)(g_Vp + (size_t)(bt * 4 + h) * 16 * 2048);

    // prefetch tile 0
#pragma unroll
    for (int j = 0; j < 4; j++) {
        CP16(&sK[0][j * 128 + tid], kg + j * 128 + tid);
        CP16(&sV[0][j * 128 + tid], vg + j * 128 + tid);
    }
    asm volatile("cp.async.commit_group;");

    for (int kt = 0; kt < 16; kt++) {
        const int cur = kt & 1;
        if (kt < 15) {
            const int nb = cur ^ 1;
            const float4* kn = kg + (kt + 1) * 512;
            const float4* vn = vg + (kt + 1) * 512;
#pragma unroll
            for (int j = 0; j < 4; j++) {
                CP16(&sK[nb][j * 128 + tid], kn + j * 128 + tid);
                CP16(&sV[nb][j * 128 + tid], vn + j * 128 + tid);
            }
            asm volatile("cp.async.commit_group;");
            asm volatile("cp.async.wait_group 1;");
        } else {
            asm volatile("cp.async.wait_group 0;");
        }
        __syncthreads();

        float S[8][4];
#pragma unroll
        for (int nt = 0; nt < 8; nt++) {
            S[nt][0] = S[nt][1] = S[nt][2] = S[nt][3] = 0.f;
#pragma unroll
            for (int dch = 0; dch < 2; dch++) {
                float4 kf = sK[cur][(nt * 2 + dch) * 32 + lane];
                mma8(S[nt], qa[2 * dch][0], qa[2 * dch][1], qa[2 * dch][2],
                     qa[2 * dch][3], kf.x, kf.y);
                mma8(S[nt], qa[2 * dch + 1][0], qa[2 * dch + 1][1],
                     qa[2 * dch + 1][2], qa[2 * dch + 1][3], kf.z, kf.w);
            }
        }

#pragma unroll
        for (int nt = 0; nt < 8; nt++) {
            S[nt][0] = ex2f(S[nt][0]);
            S[nt][1] = ex2f(S[nt][1]);
            S[nt][2] = ex2f(S[nt][2]);
            S[nt][3] = ex2f(S[nt][3]);
            l0 += S[nt][0] + S[nt][1];
            l1 += S[nt][2] + S[nt][3];
            S[nt][0] = f2tf(S[nt][0]);
            S[nt][1] = f2tf(S[nt][1]);
            S[nt][2] = f2tf(S[nt][2]);
            S[nt][3] = f2tf(S[nt][3]);
        }

#pragma unroll
        for (int kc = 0; kc < 8; kc++) {
            float a0 = S[kc][0], a1 = S[kc][2], a2 = S[kc][1], a3 = S[kc][3];
#pragma unroll
            for (int dth = 0; dth < 2; dth++) {
                float4 vf = sV[cur][(kc * 2 + dth) * 32 + lane];
                mma8(O[2 * dth], a0, a1, a2, a3, vf.x, vf.y);
                mma8(O[2 * dth + 1], a0, a1, a2, a3, vf.z, vf.w);
            }
        }
        __syncthreads();
    }

    l0 += __shfl_xor_sync(0xffffffff, l0, 1);
    l0 += __shfl_xor_sync(0xffffffff, l0, 2);
    l1 += __shfl_xor_sync(0xffffffff, l1, 1);
    l1 += __shfl_xor_sync(0xffffffff, l1, 2);
    float inv0 = 1.f / l0, inv1 = 1.f / l1;

    int q = q0 + warp * 16 + g;
    size_t ob = (size_t)(bt * 1024 + q) * 128 + h * 32;
#pragma unroll
    for (int dt = 0; dt < 4; dt++) {
        float2 v0 = {O[dt][0] * inv0, O[dt][1] * inv0};
        float2 v1 = {O[dt][2] * inv1, O[dt][3] * inv1};
        *(float2*)(g_attn + ob + dt * 8 + 2 * t4) = v0;
        *(float2*)(g_attn + ob + 8 * 128 + dt * 8 + 2 * t4) = v1;
    }
}

// ---------------------------------------------------------------------------
// Launch
// ---------------------------------------------------------------------------
extern "C" void kernel_launch(void* const* d_in, const int* in_sizes, int n_in,
                              void* d_out, int out_size) {
    const float* bev   = (const float*)d_in[0];
    const float* hd    = (const float*)d_in[1];
    const float* ego   = (const float*)d_in[2];
    const float* front = (const float*)d_in[3];
    const float* w_bev = (const float*)d_in[4];
    const float* b_bev = (const float*)d_in[5];
    const float* w_hd  = (const float*)d_in[6];
    const float* b_hd  = (const float*)d_in[7];
    const float* wq    = (const float*)d_in[8];
    const float* wk    = (const float*)d_in[9];
    const float* wv    = (const float*)d_in[10];
    const float* wo    = (const float*)d_in[11];
    const float* bo    = (const float*)d_in[12];
    const float* w_out = (const float*)d_in[13];
    const float* b_out = (const float*)d_in[14];
    float* out = (float*)d_out;

    float *p_bev_feat, *p_kv, *p_fused;
    cudaGetSymbolAddress((void**)&p_bev_feat, g_bev_feat);
    cudaGetSymbolAddress((void**)&p_kv, g_kv);
    cudaGetSymbolAddress((void**)&p_fused, g_fused);

    const float scaleQ = 0.17677669529663687f * 1.4426950408889634f;

    resize_front_kernel<<<2048, 256>>>(front);

    conv_dual_kernel<<<dim3(8, 8, 8), 256>>>(
        bev, w_bev, b_bev, p_bev_feat, 128, 128, 144,
        hd, w_hd, b_hd, p_kv, 192, 64, 64,
        ego, 4);

    proj_qkv_fused<<<dim3(16, 3, 8), 256>>>(wq, wk, wv, scaleQ);

    attn_mma_kernel<<<dim3(16, 4, 8), 128>>>();

    proj_out_mma<<<dim3(16, 8), 256>>>(wo, bo);

    conv_dual_kernel<<<dim3(4, 8, 8), 256>>>(
        p_fused, w_out, b_out, out, 128, 128, 144,
        p_fused, w_out, b_out, out, 128, 128, 144,
        ego, 4);
}

// round 6
// speedup vs baseline: 1.2304x; 1.0311x over previous
#include <cuda_runtime.h>
#include <stdint.h>

// ---------------------------------------------------------------------------
// Scratch
// ---------------------------------------------------------------------------
__device__ float g_bev_feat[8 * 128 * 1024];   // (bt, c, n)
__device__ float g_kv[8 * 192 * 1024];         // (bt, c, n)
__device__ float g_Q[8 * 4 * 1024 * 32];       // (bt,h,n,d) tf32, scaled
__device__ float g_Kp[8 * 4 * 16 * 2048];      // packed B-fragments per 64-key tile
__device__ float g_Vp[8 * 4 * 16 * 2048];      // packed (incl. sigma permutation)
__device__ float g_attn[8 * 1024 * 128];       // (bt, n, c)
__device__ float g_fused[8 * 128 * 1024];      // (bt, c, n)

// ---------------------------------------------------------------------------
// Helpers
// ---------------------------------------------------------------------------
__device__ __forceinline__ float f2tf(float x) {
    uint32_t u;
    asm("cvt.rna.tf32.f32 %0,%1;" : "=r"(u) : "f"(x));
    return __uint_as_float(u);
}
__device__ __forceinline__ float ex2f(float x) {
    float y;
    asm("ex2.approx.f32 %0,%1;" : "=f"(y) : "f"(x));
    return y;
}
__device__ __forceinline__ void mma8(float* c, float a0, float a1, float a2,
                                     float a3, float b0, float b1) {
    asm("mma.sync.aligned.m16n8k8.row.col.f32.tf32.tf32.f32 "
        "{%0,%1,%2,%3},{%4,%5,%6,%7},{%8,%9},{%0,%1,%2,%3};"
        : "+f"(c[0]), "+f"(c[1]), "+f"(c[2]), "+f"(c[3])
        : "r"(__float_as_uint(a0)), "r"(__float_as_uint(a1)),
          "r"(__float_as_uint(a2)), "r"(__float_as_uint(a3)),
          "r"(__float_as_uint(b0)), "r"(__float_as_uint(b1)));
}
#define CP16(dst, src)                                                        \
    {                                                                         \
        uint32_t _s = (uint32_t)__cvta_generic_to_shared(dst);                \
        asm volatile("cp.async.cg.shared.global [%0], [%1], 16;" ::"r"(_s),   \
                     "l"(src));                                               \
    }

// ---------------------------------------------------------------------------
// Bilinear resize 16x16 -> 32x32 (half-pixel), writes g_kv channels 128..191
// ---------------------------------------------------------------------------
__global__ __launch_bounds__(256) void resize_front_kernel(const float* __restrict__ front) {
    int idx = blockIdx.x * 256 + threadIdx.x;
    if (idx >= 8 * 64 * 1024) return;
    int px = idx & 1023, c = (idx >> 10) & 63, bt = idx >> 16;
    int y = px >> 5, x = px & 31;
    float sy = y * 0.5f - 0.25f, sx = x * 0.5f - 0.25f;
    int y0 = __float2int_rd(sy), x0 = __float2int_rd(sx);
    float fy = sy - y0, fx = sx - x0;
    int y0c = max(y0, 0), y1c = min(y0 + 1, 15);
    int x0c = max(x0, 0), x1c = min(x0 + 1, 15);
    const float* src = front + (bt * 64 + c) * 256;
    float a = src[y0c * 16 + x0c], b = src[y0c * 16 + x1c];
    float cc = src[y1c * 16 + x0c], d = src[y1c * 16 + x1c];
    float top = a + fx * (b - a), bot = cc + fx * (d - cc);
    g_kv[(size_t)(bt * 192 + 128 + c) * 1024 + px] = top + fy * (bot - top);
}

// ---------------------------------------------------------------------------
// Conv 3x3 SAME via implicit GEMM, dual-path. Weights staged in A-fragment
// order -> one LDS.128 per (om,kt). Block 32oc x 128px, 8 warps, 2 blocks/SM.
// ---------------------------------------------------------------------------
__global__ __launch_bounds__(256, 2) void conv_dual_kernel(
    const float* __restrict__ in0, const float* __restrict__ w0,
    const float* __restrict__ bias0, float* __restrict__ out0, int ld0, int cin0, int ctot0,
    const float* __restrict__ in1, const float* __restrict__ w1,
    const float* __restrict__ bias1, float* __restrict__ out1, int ld1, int cin1, int ctot1,
    const float* __restrict__ ego, int xsplit)
{
    const int path = (int)blockIdx.x >= xsplit;
    const float* in = path ? in1 : in0;
    const float* w = path ? w1 : w0;
    const float* bias = path ? bias1 : bias0;
    float* out = path ? out1 : out0;
    const int ld_out = path ? ld1 : ld0;
    const int CIN = path ? cin1 : cin0;
    const int CTOT = path ? ctot1 : ctot0;
    const int NCH = CTOT >> 3;
    const int oc_base = (path ? blockIdx.x - xsplit : blockIdx.x) * 32;
    const int y0 = blockIdx.y * 4;
    const int bt = blockIdx.z;
    const int tid = threadIdx.x;
    const int warp = tid >> 5, lane = tid & 31;
    const int g = lane >> 2, t4 = lane & 3;
    const int om = warp >> 2, pw = warp & 3;

    __shared__ float s_in[8 * 216];          // 8 ic x (6 rows x 34), stride 216
    __shared__ float s_wf[2 * 9 * 32 * 4];   // A-fragment packed: (om,kt,lane)->float4

    // staging map packed: sdst(11b) | ssrc(13b)<<11 | icl(3b)<<24
    int pack[7];
    unsigned vmask = 0, amask = 0;
#pragma unroll
    for (int s = 0; s < 7; s++) {
        int idx = tid + s * 256;
        pack[s] = 0;
        if (idx < 1632) {
            amask |= 1u << s;
            int icl = idx / 204, rem = idx - icl * 204;
            int rr = rem / 34, cc = rem - rr * 34;
            int Y = y0 - 1 + rr, X = cc - 1;
            int sdst = icl * 216 + rem;
            int ssrc = 0;
            if ((unsigned)Y < 32u && (unsigned)X < 32u) {
                vmask |= 1u << s;
                ssrc = icl * 1024 + Y * 32 + X;
            }
            pack[s] = sdst | (ssrc << 11) | (icl << 24);
        }
    }
    // weight staging: thread handles (woc, wicl), 9 taps
    const int woc = tid >> 3, wicl = tid & 7;
    const int wfbase = (woc >> 4) * 1152 + ((woc & 7) * 4 + (wicl & 3)) * 4 +
                       ((woc >> 3) & 1) + 2 * (wicl >> 2);

    float C[4][4];
#pragma unroll
    for (int nt = 0; nt < 4; nt++)
#pragma unroll
        for (int i = 0; i < 4; i++) C[nt][i] = 0.f;

    float pin[7], pwv[9];
    {
        const float* src = in + (size_t)bt * CIN * 1024;
#pragma unroll
        for (int s = 0; s < 7; s++)
            pin[s] = (vmask >> s & 1) ? __ldg(src + ((pack[s] >> 11) & 0x1FFF)) : 0.f;
        const float* wp = w + ((size_t)(oc_base + woc) * CTOT + wicl) * 9;
#pragma unroll
        for (int j = 0; j < 9; j++) pwv[j] = __ldg(wp + j);
    }

    for (int ch = 0; ch < NCH; ch++) {
#pragma unroll
        for (int s = 0; s < 7; s++)
            if (amask >> s & 1) s_in[pack[s] & 0x7FF] = f2tf(pin[s]);
#pragma unroll
        for (int j = 0; j < 9; j++) s_wf[wfbase + j * 128] = f2tf(pwv[j]);
        __syncthreads();

        if (ch + 1 < NCH) {
            int ic0 = (ch + 1) * 8;
            if (ic0 < CIN) {
                const float* src = in + (size_t)(bt * CIN + ic0) * 1024;
#pragma unroll
                for (int s = 0; s < 7; s++)
                    pin[s] = (vmask >> s & 1) ? __ldg(src + ((pack[s] >> 11) & 0x1FFF)) : 0.f;
            } else {
                const float* e = ego + bt * 16 + (ic0 - CIN);
#pragma unroll
                for (int s = 0; s < 7; s++)
                    pin[s] = (vmask >> s & 1) ? __ldg(e + ((pack[s] >> 24) & 7)) : 0.f;
            }
            const float* wp = w + ((size_t)(oc_base + woc) * CTOT + ic0 + wicl) * 9;
#pragma unroll
            for (int j = 0; j < 9; j++) pwv[j] = __ldg(wp + j);
        }

        const float4* swf4 = (const float4*)s_wf;
#pragma unroll
        for (int kt = 0; kt < 9; kt++) {
            const int dy = kt / 3, dx = kt % 3;
            float4 af = swf4[om * 288 + kt * 32 + lane];
#pragma unroll
            for (int nt = 0; nt < 4; nt++) {
                int base = (pw + dy) * 34 + nt * 8 + g + dx;
                float b0 = s_in[t4 * 216 + base];
                float b1 = s_in[(t4 + 4) * 216 + base];
                mma8(C[nt], af.x, af.y, af.z, af.w, b0, b1);
            }
        }
        __syncthreads();
    }

    const int o0 = oc_base + om * 16 + g, o1 = o0 + 8;
    const float bv0 = bias[o0], bv1 = bias[o1];
    const int y = y0 + pw;
#pragma unroll
    for (int nt = 0; nt < 4; nt++) {
        int px = y * 32 + nt * 8 + 2 * t4;
        float2 v0 = {fmaxf(C[nt][0] + bv0, 0.f), fmaxf(C[nt][1] + bv0, 0.f)};
        float2 v1 = {fmaxf(C[nt][2] + bv1, 0.f), fmaxf(C[nt][3] + bv1, 0.f)};
        *(float2*)(out + (size_t)(bt * ld_out + o0) * 1024 + px) = v0;
        *(float2*)(out + (size_t)(bt * ld_out + o1) * 1024 + px) = v1;
    }
}

// ---------------------------------------------------------------------------
// Fused Q/K/V projection, 16-k staging, W in A-fragment order.
// Q -> g_Q (scaled tf32); K -> g_Kp, V -> g_Vp fragment-packed for attention.
// ---------------------------------------------------------------------------
__global__ __launch_bounds__(256) void proj_qkv_fused(
    const float* __restrict__ Wq, const float* __restrict__ Wk,
    const float* __restrict__ Wv, float scaleQ)
{
    const int which = blockIdx.y;
    const float* X = which == 0 ? g_bev_feat : g_kv;
    const float* W = which == 0 ? Wq : (which == 1 ? Wk : Wv);
    const int Cdim = which == 0 ? 128 : 192;

    const int n0 = (blockIdx.x & 7) * 128;
    const int o_base = (blockIdx.x >> 3) * 64;
    const int bt = blockIdx.z;
    const int tid = threadIdx.x;
    const int warp = tid >> 5, lane = tid & 31;
    const int g = lane >> 2, t4 = lane & 3;
    const int om = warp >> 1, nw = warp & 1;

    __shared__ float sX[16 * 136];
    __shared__ float sWf[8 * 32 * 4];   // (s*4+frag, lane) -> float4

    float C[8][4];
#pragma unroll
    for (int nt = 0; nt < 8; nt++)
#pragma unroll
        for (int i = 0; i < 4; i++) C[nt][i] = 0.f;

    const int xk = tid >> 5, xn = lane * 4;
    const int wo = tid & 63, wk4 = (tid >> 6) * 4;
    // fragment positions for the 4 staged W values (k = wk4 + i)
    int widx[4];
#pragma unroll
    for (int i = 0; i < 4; i++) {
        int k = wk4 + i, s = k >> 3, kk = k & 7;
        widx[i] = ((s * 4 + (wo >> 4)) * 32 + (wo & 7) * 4 + (kk & 3)) * 4 +
                  ((wo >> 3) & 1) + 2 * (kk >> 2);
    }

    float4 pxa = *(const float4*)(X + (size_t)(bt * Cdim + xk) * 1024 + n0 + xn);
    float4 pxb = *(const float4*)(X + (size_t)(bt * Cdim + xk + 8) * 1024 + n0 + xn);
    float4 pw4 = *(const float4*)(W + (size_t)(o_base + wo) * Cdim + wk4);

    const int NS = Cdim >> 4;
    for (int st = 0; st < NS; st++) {
        float4 va = {f2tf(pxa.x), f2tf(pxa.y), f2tf(pxa.z), f2tf(pxa.w)};
        float4 vb = {f2tf(pxb.x), f2tf(pxb.y), f2tf(pxb.z), f2tf(pxb.w)};
        *(float4*)&sX[xk * 136 + xn] = va;
        *(float4*)&sX[(xk + 8) * 136 + xn] = vb;
        sWf[widx[0]] = f2tf(pw4.x);
        sWf[widx[1]] = f2tf(pw4.y);
        sWf[widx[2]] = f2tf(pw4.z);
        sWf[widx[3]] = f2tf(pw4.w);
        __syncthreads();
        if (st + 1 < NS) {
            int c0 = (st + 1) * 16;
            pxa = *(const float4*)(X + (size_t)(bt * Cdim + c0 + xk) * 1024 + n0 + xn);
            pxb = *(const float4*)(X + (size_t)(bt * Cdim + c0 + xk + 8) * 1024 + n0 + xn);
            pw4 = *(const float4*)(W + (size_t)(o_base + wo) * Cdim + c0 + wk4);
        }
        const float4* swf4 = (const float4*)sWf;
#pragma unroll
        for (int s = 0; s < 2; s++) {
            float4 af = swf4[(s * 4 + om) * 32 + lane];
#pragma unroll
            for (int nt = 0; nt < 8; nt++) {
                float b0 = sX[(s * 8 + t4) * 136 + nw * 64 + nt * 8 + g];
                float b1 = sX[(s * 8 + t4 + 4) * 136 + nw * 64 + nt * 8 + g];
                mma8(C[nt], af.x, af.y, af.z, af.w, b0, b1);
            }
        }
        __syncthreads();
    }

    const int o0 = o_base + om * 16 + g, o1 = o0 + 8;
    if (which == 0) {
        size_t b0 = (size_t)(bt * 4 + (o0 >> 5)) * 32768 + (o0 & 31);
        size_t b1 = (size_t)(bt * 4 + (o1 >> 5)) * 32768 + (o1 & 31);
#pragma unroll
        for (int nt = 0; nt < 8; nt++) {
            int n = n0 + nw * 64 + nt * 8 + 2 * t4;
            g_Q[b0 + (size_t)n * 32] = f2tf(C[nt][0] * scaleQ);
            g_Q[b0 + (size_t)(n + 1) * 32] = f2tf(C[nt][1] * scaleQ);
            g_Q[b1 + (size_t)n * 32] = f2tf(C[nt][2] * scaleQ);
            g_Q[b1 + (size_t)(n + 1) * 32] = f2tf(C[nt][3] * scaleQ);
        }
    } else {
        const int h = o0 >> 5;
        const int tile64 = (blockIdx.x & 7) * 2 + nw;
        const int dh = om & 1;
        float* base = (which == 1 ? g_Kp : g_Vp) +
                      (size_t)((bt * 4 + h) * 16 + tile64) * 2048;
        if (which == 1) {
#pragma unroll
            for (int nt = 0; nt < 8; nt++) {
                int foff = ((nt * 2 + dh) * 32 + 8 * t4 + (g & 3)) * 4 + (g >> 2);
                base[foff]      = f2tf(C[nt][0]);
                base[foff + 16] = f2tf(C[nt][1]);
                base[foff + 2]  = f2tf(C[nt][2]);
                base[foff + 18] = f2tf(C[nt][3]);
            }
        } else {
#pragma unroll
            for (int nt = 0; nt < 8; nt++) {
                int foff = ((nt * 2 + dh) * 32 + g * 4 + t4) * 4;
                float4 v = {f2tf(C[nt][0]), f2tf(C[nt][1]),
                            f2tf(C[nt][2]), f2tf(C[nt][3])};
                *(float4*)(base + foff) = v;
            }
        }
    }
}

// ---------------------------------------------------------------------------
// Output projection, 16-k staging, W fragment-packed.
// ---------------------------------------------------------------------------
__global__ __launch_bounds__(256) void proj_out_mma(
    const float* __restrict__ W, const float* __restrict__ bias)
{
    const int n0 = (blockIdx.x & 7) * 128;
    const int o_base = (blockIdx.x >> 3) * 64;
    const int bt = blockIdx.y;
    const int tid = threadIdx.x;
    const int warp = tid >> 5, lane = tid & 31;
    const int g = lane >> 2, t4 = lane & 3;
    const int om = warp >> 1, nw = warp & 1;

    __shared__ float sX[16 * 136];
    __shared__ float sWf[8 * 32 * 4];

    float C[8][4];
#pragma unroll
    for (int nt = 0; nt < 8; nt++)
#pragma unroll
        for (int i = 0; i < 4; i++) C[nt][i] = 0.f;

    const int xn = tid & 127, xc4 = (tid >> 7) * 4;
    const int wo = tid & 63, wk4 = (tid >> 6) * 4;
    int widx[4];
#pragma unroll
    for (int i = 0; i < 4; i++) {
        int k = wk4 + i, s = k >> 3, kk = k & 7;
        widx[i] = ((s * 4 + (wo >> 4)) * 32 + (wo & 7) * 4 + (kk & 3)) * 4 +
                  ((wo >> 3) & 1) + 2 * (kk >> 2);
    }

    float4 pxa = *(const float4*)(g_attn + (size_t)(bt * 1024 + n0 + xn) * 128 + xc4);
    float4 pxb = *(const float4*)(g_attn + (size_t)(bt * 1024 + n0 + xn) * 128 + xc4 + 8);
    float4 pw4 = *(const float4*)(W + (size_t)(o_base + wo) * 128 + wk4);

    for (int st = 0; st < 8; st++) {
        sX[(xc4 + 0) * 136 + xn] = f2tf(pxa.x);
        sX[(xc4 + 1) * 136 + xn] = f2tf(pxa.y);
        sX[(xc4 + 2) * 136 + xn] = f2tf(pxa.z);
        sX[(xc4 + 3) * 136 + xn] = f2tf(pxa.w);
        sX[(xc4 + 8) * 136 + xn] = f2tf(pxb.x);
        sX[(xc4 + 9) * 136 + xn] = f2tf(pxb.y);
        sX[(xc4 + 10) * 136 + xn] = f2tf(pxb.z);
        sX[(xc4 + 11) * 136 + xn] = f2tf(pxb.w);
        sWf[widx[0]] = f2tf(pw4.x);
        sWf[widx[1]] = f2tf(pw4.y);
        sWf[widx[2]] = f2tf(pw4.z);
        sWf[widx[3]] = f2tf(pw4.w);
        __syncthreads();
        if (st + 1 < 8) {
            int c0 = (st + 1) * 16;
            pxa = *(const float4*)(g_attn + (size_t)(bt * 1024 + n0 + xn) * 128 + c0 + xc4);
            pxb = *(const float4*)(g_attn + (size_t)(bt * 1024 + n0 + xn) * 128 + c0 + xc4 + 8);
            pw4 = *(const float4*)(W + (size_t)(o_base + wo) * 128 + c0 + wk4);
        }
        const float4* swf4 = (const float4*)sWf;
#pragma unroll
        for (int s = 0; s < 2; s++) {
            float4 af = swf4[(s * 4 + om) * 32 + lane];
#pragma unroll
            for (int nt = 0; nt < 8; nt++) {
                float b0 = sX[(s * 8 + t4) * 136 + nw * 64 + nt * 8 + g];
                float b1 = sX[(s * 8 + t4 + 4) * 136 + nw * 64 + nt * 8 + g];
                mma8(C[nt], af.x, af.y, af.z, af.w, b0, b1);
            }
        }
        __syncthreads();
    }

    const int o0 = o_base + om * 16 + g, o1 = o0 + 8;
    const float bv0 = bias[o0], bv1 = bias[o1];
#pragma unroll
    for (int nt = 0; nt < 8; nt++) {
        int n = n0 + nw * 64 + nt * 8 + 2 * t4;
        float2 v0 = {C[nt][0] + bv0, C[nt][1] + bv0};
        float2 v1 = {C[nt][2] + bv1, C[nt][3] + bv1};
        *(float2*)(g_fused + (size_t)(bt * 128 + o0) * 1024 + n) = v0;
        *(float2*)(g_fused + (size_t)(bt * 128 + o1) * 1024 + n) = v1;
    }
}

// ---------------------------------------------------------------------------
// Flash attention, fragment-native (unchanged from R5).
// ---------------------------------------------------------------------------
__global__ __launch_bounds__(128) void attn_mma_kernel() {
    const int q0 = blockIdx.x * 64;
    const int h = blockIdx.y;
    const int bt = blockIdx.z;
    const int tid = threadIdx.x;
    const int warp = tid >> 5, lane = tid & 31;
    const int g = lane >> 2, t4 = lane & 3;

    __shared__ __align__(16) float4 sK[2][512];
    __shared__ __align__(16) float4 sV[2][512];

    float qa[4][4];
    {
        const float* qp = g_Q + ((size_t)(bt * 4 + h) * 1024 + q0 + warp * 16) * 32;
#pragma unroll
        for (int dc = 0; dc < 4; dc++) {
            qa[dc][0] = qp[g * 32 + dc * 8 + t4];
            qa[dc][1] = qp[(g + 8) * 32 + dc * 8 + t4];
            qa[dc][2] = qp[g * 32 + dc * 8 + t4 + 4];
            qa[dc][3] = qp[(g + 8) * 32 + dc * 8 + t4 + 4];
        }
    }

    float O[4][4];
#pragma unroll
    for (int dt = 0; dt < 4; dt++)
#pragma unroll
        for (int i = 0; i < 4; i++) O[dt][i] = 0.f;
    float l0 = 0.f, l1 = 0.f;

    const float4* kg = (const float4*)(g_Kp + (size_t)(bt * 4 + h) * 16 * 2048);
    const float4* vg = (const float4*)(g_Vp + (size_t)(bt * 4 + h) * 16 * 2048);

#pragma unroll
    for (int j = 0; j < 4; j++) {
        CP16(&sK[0][j * 128 + tid], kg + j * 128 + tid);
        CP16(&sV[0][j * 128 + tid], vg + j * 128 + tid);
    }
    asm volatile("cp.async.commit_group;");

    for (int kt = 0; kt < 16; kt++) {
        const int cur = kt & 1;
        if (kt < 15) {
            const int nb = cur ^ 1;
            const float4* kn = kg + (kt + 1) * 512;
            const float4* vn = vg + (kt + 1) * 512;
#pragma unroll
            for (int j = 0; j < 4; j++) {
                CP16(&sK[nb][j * 128 + tid], kn + j * 128 + tid);
                CP16(&sV[nb][j * 128 + tid], vn + j * 128 + tid);
            }
            asm volatile("cp.async.commit_group;");
            asm volatile("cp.async.wait_group 1;");
        } else {
            asm volatile("cp.async.wait_group 0;");
        }
        __syncthreads();

        float S[8][4];
#pragma unroll
        for (int nt = 0; nt < 8; nt++) {
            S[nt][0] = S[nt][1] = S[nt][2] = S[nt][3] = 0.f;
#pragma unroll
            for (int dch = 0; dch < 2; dch++) {
                float4 kf = sK[cur][(nt * 2 + dch) * 32 + lane];
                mma8(S[nt], qa[2 * dch][0], qa[2 * dch][1], qa[2 * dch][2],
                     qa[2 * dch][3], kf.x, kf.y);
                mma8(S[nt], qa[2 * dch + 1][0], qa[2 * dch + 1][1],
                     qa[2 * dch + 1][2], qa[2 * dch + 1][3], kf.z, kf.w);
            }
        }

#pragma unroll
        for (int nt = 0; nt < 8; nt++) {
            S[nt][0] = ex2f(S[nt][0]);
            S[nt][1] = ex2f(S[nt][1]);
            S[nt][2] = ex2f(S[nt][2]);
            S[nt][3] = ex2f(S[nt][3]);
            l0 += S[nt][0] + S[nt][1];
            l1 += S[nt][2] + S[nt][3];
            S[nt][0] = f2tf(S[nt][0]);
            S[nt][1] = f2tf(S[nt][1]);
            S[nt][2] = f2tf(S[nt][2]);
            S[nt][3] = f2tf(S[nt][3]);
        }

#pragma unroll
        for (int kc = 0; kc < 8; kc++) {
            float a0 = S[kc][0], a1 = S[kc][2], a2 = S[kc][1], a3 = S[kc][3];
#pragma unroll
            for (int dth = 0; dth < 2; dth++) {
                float4 vf = sV[cur][(kc * 2 + dth) * 32 + lane];
                mma8(O[2 * dth], a0, a1, a2, a3, vf.x, vf.y);
                mma8(O[2 * dth + 1], a0, a1, a2, a3, vf.z, vf.w);
            }
        }
        __syncthreads();
    }

    l0 += __shfl_xor_sync(0xffffffff, l0, 1);
    l0 += __shfl_xor_sync(0xffffffff, l0, 2);
    l1 += __shfl_xor_sync(0xffffffff, l1, 1);
    l1 += __shfl_xor_sync(0xffffffff, l1, 2);
    float inv0 = 1.f / l0, inv1 = 1.f / l1;

    int q = q0 + warp * 16 + g;
    size_t ob = (size_t)(bt * 1024 + q) * 128 + h * 32;
#pragma unroll
    for (int dt = 0; dt < 4; dt++) {
        float2 v0 = {O[dt][0] * inv0, O[dt][1] * inv0};
        float2 v1 = {O[dt][2] * inv1, O[dt][3] * inv1};
        *(float2*)(g_attn + ob + dt * 8 + 2 * t4) = v0;
        *(float2*)(g_attn + ob + 8 * 128 + dt * 8 + 2 * t4) = v1;
    }
}

// ---------------------------------------------------------------------------
// Launch
// ---------------------------------------------------------------------------
extern "C" void kernel_launch(void* const* d_in, const int* in_sizes, int n_in,
                              void* d_out, int out_size) {
    const float* bev   = (const float*)d_in[0];
    const float* hd    = (const float*)d_in[1];
    const float* ego   = (const float*)d_in[2];
    const float* front = (const float*)d_in[3];
    const float* w_bev = (const float*)d_in[4];
    const float* b_bev = (const float*)d_in[5];
    const float* w_hd  = (const float*)d_in[6];
    const float* b_hd  = (const float*)d_in[7];
    const float* wq    = (const float*)d_in[8];
    const float* wk    = (const float*)d_in[9];
    const float* wv    = (const float*)d_in[10];
    const float* wo    = (const float*)d_in[11];
    const float* bo    = (const float*)d_in[12];
    const float* w_out = (const float*)d_in[13];
    const float* b_out = (const float*)d_in[14];
    float* out = (float*)d_out;

    float *p_bev_feat, *p_kv, *p_fused;
    cudaGetSymbolAddress((void**)&p_bev_feat, g_bev_feat);
    cudaGetSymbolAddress((void**)&p_kv, g_kv);
    cudaGetSymbolAddress((void**)&p_fused, g_fused);

    const float scaleQ = 0.17677669529663687f * 1.4426950408889634f;

    resize_front_kernel<<<2048, 256>>>(front);

    conv_dual_kernel<<<dim3(8, 8, 8), 256>>>(
        bev, w_bev, b_bev, p_bev_feat, 128, 128, 144,
        hd, w_hd, b_hd, p_kv, 192, 64, 64,
        ego, 4);

    proj_qkv_fused<<<dim3(16, 3, 8), 256>>>(wq, wk, wv, scaleQ);

    attn_mma_kernel<<<dim3(16, 4, 8), 128>>>();

    proj_out_mma<<<dim3(16, 8), 256>>>(wo, bo);

    conv_dual_kernel<<<dim3(4, 8, 8), 256>>>(
        p_fused, w_out, b_out, out, 128, 128, 144,
        p_fused, w_out, b_out, out, 128, 128, 144,
        ego, 4);
}